// round 15
// baseline (speedup 1.0000x reference)
#include <cuda_runtime.h>
#include <math.h>

#define BSZ 32
#define QN  600
#define NC  152
#define TT  32
#define NT  1024          // BSZ*TT
#define NR  19200         // BSZ*QN

#define CTH 512           // 16 warps
#define RPB 16            // rows per cost block
#define NMATCH 64
#define NCOSTB 1200       // cost blocks per which: NR / RPB

// per-match-block diagonal tile: g_tile[blk][q][t]
__device__ float g_tile[NMATCH][QN][TT];

__device__ __forceinline__ unsigned fmap(float f) {
    unsigned b = __float_as_uint(f);
    return b ^ (unsigned)(((int)b >> 31) | 0x80000000);
}
__device__ __forceinline__ float funmap(unsigned m) {
    return __uint_as_float((m & 0x80000000u) ? (m ^ 0x80000000u) : ~m);
}

#define PSTRIDE 153
struct CostSmem {                  // ~10.4 KB
    float s_prob[RPB][PSTRIDE];    // (softmax prob - 1) per row
    float s_rbox[RPB][12];         // cx,cy,w,h | x0,y0,x1,y1 | area,pad..
};

#define NW 16
#define KS 2
struct MatchSmem {
    float  u[34];
    unsigned long long s_rm[TT];
    unsigned long long red[2][NW];
    int    rowarg[TT];
    int    unrows[TT];
    int    nun_s, cnt;
    int    sq[TT], sr[TT];
    int    way[QN];
    int    p[QN];
    float4 t_box[TT];
    float4 t_xy[TT];
    float  t_ta[TT];
    int    t_id[TT];
};

// ---------------------------------------------------------------------------
// cost for one (pred, target) pair. Takes (prob - 1); two MUFU reciprocals:
// cost = l1 - (prob-1) - inter*rcp(uni) - uni*rcp(ac)
// ---------------------------------------------------------------------------
__device__ __forceinline__ float pair_cost(
    float ocx, float ocy, float ow, float oh,
    float ox0, float oy0, float ox1, float oy1, float oarea,
    float tcx, float tcy, float tw, float th,
    float tx0, float ty0, float tx1, float ty1, float ta, float probm1)
{
    float l1 = fabsf(ocx - tcx) + fabsf(ocy - tcy)
             + fabsf(ow - tw)  + fabsf(oh - th);
    float ltx = fmaxf(ox0, tx0), lty = fmaxf(oy0, ty0);
    float rbx = fminf(ox1, tx1), rby = fminf(oy1, ty1);
    float iwr = rbx - ltx, ihr = rby - lty;
    float inter = fmaxf(iwr, 0.f) * fmaxf(ihr, 0.f);
    float uni   = oarea + ta - inter;
    float wc = ow + tw - iwr;          // enclosing width (identity, exact)
    float hc = oh + th - ihr;
    float ac = wc * hc;
    float rcpu = __fdividef(1.f, uni); // MUFU.RCP
    float rcpa = __fdividef(1.f, ac);  // MUFU.RCP
    float c = l1 - probm1;
    c = fmaf(-inter, rcpu, c);
    c = fmaf(-uni,  rcpa, c);
    return c;
}

// ---------------------------------------------------------------------------
// Cost path: 16 rows per block (1 row per warp preamble); targets resident
// in registers (2 adjacent per lane); paired float2 streaming store.
// ---------------------------------------------------------------------------
__device__ void run_cost(
    CostSmem& sm, int xb, int which,
    const float* __restrict__ logits, const float* __restrict__ boxes,
    const float* __restrict__ tbbox,  const int* __restrict__ tids,
    float* __restrict__ out)
{
    float* __restrict__ C = out + (size_t)which * ((size_t)NR * NT);
    const int tid = threadIdx.x;
    const int warp = tid >> 5, lane = tid & 31;
    const int row0 = xb * RPB;

    // preamble: warp w handles row w (softmax + row box table)
    {
        const int r = warp;
        const int row = row0 + r;
        const float* lrow = logits + (size_t)row * NC;
        float rg[5], m = -1e30f;
        #pragma unroll
        for (int jj = 0; jj < 5; jj++) {
            int k = lane + 32 * jj;
            rg[jj] = (k < NC) ? lrow[k] : -1e30f;
            m = fmaxf(m, rg[jj]);
        }
        #pragma unroll
        for (int o = 16; o; o >>= 1) m = fmaxf(m, __shfl_xor_sync(~0u, m, o));
        float s = 0.f;
        #pragma unroll
        for (int jj = 0; jj < 5; jj++) {
            int k = lane + 32 * jj;
            if (k < NC) { rg[jj] = __expf(rg[jj] - m); s += rg[jj]; }
        }
        #pragma unroll
        for (int o = 16; o; o >>= 1) s += __shfl_xor_sync(~0u, s, o);
        const float inv = __fdividef(1.f, s);
        #pragma unroll
        for (int jj = 0; jj < 5; jj++) {
            int k = lane + 32 * jj;
            if (k < NC) sm.s_prob[r][k] = fmaf(rg[jj], inv, -1.0f); // prob-1
        }
        if (lane == 0) {
            float4 pb = *reinterpret_cast<const float4*>(boxes + (size_t)row * 4);
            float x0 = pb.x - 0.5f*pb.z, y0 = pb.y - 0.5f*pb.w;
            float x1 = pb.x + 0.5f*pb.z, y1 = pb.y + 0.5f*pb.w;
            sm.s_rbox[r][0] = pb.x; sm.s_rbox[r][1] = pb.y;
            sm.s_rbox[r][2] = pb.z; sm.s_rbox[r][3] = pb.w;
            sm.s_rbox[r][4] = x0;   sm.s_rbox[r][5] = y0;
            sm.s_rbox[r][6] = x1;   sm.s_rbox[r][7] = y1;
            sm.s_rbox[r][8] = (x1 - x0) * (y1 - y0);
        }
    }
    __syncthreads();

    // targets: 2 ADJACENT per lane, resident in registers
    const int t0 = warp * 64 + lane * 2;
    const float4 b0 = *reinterpret_cast<const float4*>(tbbox + (size_t)t0 * 4);
    const float4 b1 = *reinterpret_cast<const float4*>(tbbox + (size_t)(t0+1) * 4);
    const float ax0 = b0.x - 0.5f*b0.z, ay0 = b0.y - 0.5f*b0.w;
    const float ax1 = b0.x + 0.5f*b0.z, ay1 = b0.y + 0.5f*b0.w;
    const float ta0 = (ax1 - ax0) * (ay1 - ay0);
    const float bx0_ = b1.x - 0.5f*b1.z, by0_ = b1.y - 0.5f*b1.w;
    const float bx1_ = b1.x + 0.5f*b1.z, by1_ = b1.y + 0.5f*b1.w;
    const float ta1 = (bx1_ - bx0_) * (by1_ - by0_);
    const int id0 = tids[t0], id1 = tids[t0 + 1];

    float* cp = C + (size_t)row0 * NT;
    #pragma unroll 2
    for (int r = 0; r < RPB; r++) {
        const float4 rc = *reinterpret_cast<const float4*>(&sm.s_rbox[r][0]);
        const float4 rx = *reinterpret_cast<const float4*>(&sm.s_rbox[r][4]);
        const float  ra = sm.s_rbox[r][8];
        const float pr0 = sm.s_prob[r][id0];
        const float pr1 = sm.s_prob[r][id1];
        float2 v;
        v.x = pair_cost(rc.x, rc.y, rc.z, rc.w,
                        rx.x, rx.y, rx.z, rx.w, ra,
                        b0.x, b0.y, b0.z, b0.w,
                        ax0, ay0, ax1, ay1, ta0, pr0);
        v.y = pair_cost(rc.x, rc.y, rc.z, rc.w,
                        rx.x, rx.y, rx.z, rx.w, ra,
                        b1.x, b1.y, b1.z, b1.w,
                        bx0_, by0_, bx1_, by1_, ta1, pr1);
        __stcs(reinterpret_cast<float2*>(cp + t0), v);   // STG.64
        cp += NT;
    }
}

// ---------------------------------------------------------------------------
// Match path: self-computed diag tile -> g_tile, rowmin warm start, exact
// Dijkstra finish, ranked emit. 512 threads.
// ---------------------------------------------------------------------------
__device__ void run_match(
    MatchSmem& sm, int bi, int b, int which,
    const float* __restrict__ logits, const float* __restrict__ boxes,
    const float* __restrict__ tbbox,  const int* __restrict__ tids,
    float* __restrict__ outbase)
{
    const int tid  = threadIdx.x;
    const int warp = tid >> 5, lane = tid & 31;

    if (tid < TT) {
        int j = b * TT + tid;
        float4 t = *reinterpret_cast<const float4*>(tbbox + (size_t)j * 4);
        sm.t_box[tid] = t;
        float x0 = t.x - 0.5f*t.z, y0 = t.y - 0.5f*t.w;
        float x1 = t.x + 0.5f*t.z, y1 = t.y + 0.5f*t.w;
        sm.t_xy[tid] = make_float4(x0, y0, x1, y1);
        sm.t_ta[tid] = (x1 - x0) * (y1 - y0);
        sm.t_id[tid] = tids[j];
        sm.s_rm[tid] = ~0ull;
    }
    for (int j = tid; j < QN; j += CTH) sm.p[j] = 0;
    __syncthreads();

    // build tile: warp per prediction row q (stride NW); lane = target t
    const int t = lane;
    const float4 tb  = sm.t_box[t];
    const float4 txy = sm.t_xy[t];
    const float  ta  = sm.t_ta[t];
    const int    tclass = sm.t_id[t];
    unsigned long long lmin = ~0ull;

    for (int q = warp; q < QN; q += NW) {
        const float* lrow = logits + (size_t)(b * QN + q) * NC;
        float r[5], m = -1e30f;
        #pragma unroll
        for (int jj = 0; jj < 5; jj++) {
            int kk = lane + 32 * jj;
            r[jj] = (kk < NC) ? lrow[kk] : -1e30f;
            m = fmaxf(m, r[jj]);
        }
        #pragma unroll
        for (int o = 16; o; o >>= 1) m = fmaxf(m, __shfl_xor_sync(~0u, m, o));
        float s = 0.f;
        #pragma unroll
        for (int jj = 0; jj < 5; jj++) {
            int kk = lane + 32 * jj;
            if (kk < NC) s += __expf(r[jj] - m);
        }
        #pragma unroll
        for (int o = 16; o; o >>= 1) s += __shfl_xor_sync(~0u, s, o);
        const float inv = __fdividef(1.f, s);

        const float4 pb = *reinterpret_cast<const float4*>(boxes + (size_t)(b*QN + q)*4);
        const float ox0 = pb.x - 0.5f*pb.z, oy0 = pb.y - 0.5f*pb.w;
        const float ox1 = pb.x + 0.5f*pb.z, oy1 = pb.y + 0.5f*pb.w;
        const float oarea = (ox1 - ox0) * (oy1 - oy0);

        const float probm1 = fmaf(__expf(lrow[tclass] - m), inv, -1.0f);
        const float val = pair_cost(pb.x, pb.y, pb.z, pb.w,
                                    ox0, oy0, ox1, oy1, oarea,
                                    tb.x, tb.y, tb.z, tb.w,
                                    txy.x, txy.y, txy.z, txy.w, ta, probm1);
        g_tile[bi][q][t] = val;
        unsigned long long key = ((unsigned long long)fmap(val) << 32) | (unsigned)q;
        lmin = min(lmin, key);
    }
    atomicMin(&sm.s_rm[lane], lmin);
    __syncthreads();

    if (tid < TT) {
        unsigned long long key = sm.s_rm[tid];
        sm.u[tid + 1]  = funmap((unsigned)(key >> 32));
        sm.rowarg[tid] = (int)(unsigned)key;
    }
    __syncthreads();

    // greedy tight-edge warm start
    if (tid == 0) {
        int nun = 0;
        for (int i = 1; i <= TT; i++) {
            int q = sm.rowarg[i - 1];
            if (sm.p[q] == 0) sm.p[q] = i;
            else sm.unrows[nun++] = i;
        }
        sm.nun_s = nun;
    }
    __syncthreads();
    const int nun = sm.nun_s;

    // shortest augmenting paths for leftover rows
    const int c_[KS] = { tid, tid + CTH };
    float v_[KS] = {0.f, 0.f};
    int par = 0;

    for (int ii = 0; ii < nun; ii++) {
        const int i = sm.unrows[ii];
        float s_[KS] = {1e30f, 1e30f};
        int usedm = (c_[1] < QN) ? 0 : 2;
        int j0 = -1, i0 = i, jf;
        float off = 0.f;

        for (;;) {
            #pragma unroll
            for (int k = 0; k < KS; k++)
                if (j0 == c_[k]) usedm |= 1 << k;

            const float ui0p = sm.u[i0] - off;
            const int   trow = i0 - 1;

            float lm = 1e30f; int lidx = 0x7fffffff;
            #pragma unroll
            for (int k = 0; k < KS; k++) {
                if (!((usedm >> k) & 1)) {
                    float cur = g_tile[bi][c_[k]][trow] - ui0p - v_[k];
                    if (cur < s_[k]) { s_[k] = cur; sm.way[c_[k]] = j0; }
                    if (s_[k] < lm) { lm = s_[k]; lidx = c_[k]; }
                }
            }
            unsigned mu   = fmap(lm);
            unsigned wmin = __reduce_min_sync(~0u, mu);
            unsigned cand = (mu == wmin) ? (unsigned)lidx : 0xffffffffu;
            unsigned widx = __reduce_min_sync(~0u, cand);
            if (lane == 0)
                sm.red[par][warp] = ((unsigned long long)wmin << 32) | widx;
            __syncthreads();
            unsigned long long bp = sm.red[par][0];
            #pragma unroll
            for (int w = 1; w < NW; w++) bp = min(bp, sm.red[par][w]);
            par ^= 1;
            off = funmap((unsigned)(bp >> 32));
            const int bj = (int)(unsigned)bp;
            const int prj = sm.p[bj];
            if (prj == 0) { jf = bj; break; }
            i0 = prj; j0 = bj;
        }

        #pragma unroll
        for (int k = 0; k < KS; k++) {
            if (((usedm >> k) & 1) && c_[k] < QN) {
                float dv = off - s_[k];
                v_[k] -= dv;
                sm.u[sm.p[c_[k]]] += dv;
            }
        }
        __syncthreads();
        if (tid == 0) {
            sm.u[i] += off;
            int j = jf;
            for (;;) {
                int jp = sm.way[j];
                sm.p[j] = (jp < 0) ? i : sm.p[jp];
                if (jp < 0) break;
                j = jp;
            }
        }
        __syncthreads();
    }

    // emit: compact assigned pairs, rank by column, write
    if (tid == 0) sm.cnt = 0;
    __syncthreads();
    #pragma unroll
    for (int k = 0; k < KS; k++) {
        int q = c_[k];
        if (q < QN && sm.p[q]) {
            int tt = atomicAdd(&sm.cnt, 1);
            sm.sq[tt] = q;
            sm.sr[tt] = sm.p[q] - 1;
        }
    }
    __syncthreads();
    if (tid < TT) {
        int q = sm.sq[tid], r = sm.sr[tid];
        int rank = 0;
        #pragma unroll
        for (int o = 0; o < TT; o++)
            rank += (__shfl_sync(~0u, q, o) < q) ? 1 : 0;
        float* op = outbase + (size_t)2 * NR * NT + (size_t)which * 2 * NT; // ps/po
        float* ot = op + NT;                                                // ts/to
        op[b * TT + rank] = (float)q;
        ot[b * TT + rank] = (float)r;
    }
}

// ---------------------------------------------------------------------------
// Fused kernel: blocks [0,64) = match (wave-1, hidden under cost), rest cost.
// ---------------------------------------------------------------------------
__global__ __launch_bounds__(CTH, 2) void fused_kernel(
    const float* __restrict__ lg0, const float* __restrict__ lg1,
    const float* __restrict__ bx0, const float* __restrict__ bx1,
    const float* __restrict__ tb0, const float* __restrict__ tb1,
    const int*   __restrict__ id0, const int*   __restrict__ id1,
    float* __restrict__ out)
{
    extern __shared__ unsigned char smem_raw[];
    const int bi = blockIdx.x;

    if (bi < NMATCH) {
        const int b = bi & 31, which = bi >> 5;
        run_match(*reinterpret_cast<MatchSmem*>(smem_raw), bi, b, which,
                  which ? lg1 : lg0, which ? bx1 : bx0,
                  which ? tb1 : tb0, which ? id1 : id0, out);
    } else {
        const int cb = bi - NMATCH;
        const int which = cb / NCOSTB, xb = cb % NCOSTB;
        run_cost(*reinterpret_cast<CostSmem*>(smem_raw), xb, which,
                 which ? lg1 : lg0, which ? bx1 : bx0,
                 which ? tb1 : tb0, which ? id1 : id0, out);
    }
}

// ---------------------------------------------------------------------------
extern "C" void kernel_launch(void* const* d_in, const int* in_sizes, int n_in,
                              void* d_out, int out_size) {
    const float* lg0 = (const float*)d_in[0];
    const float* lg1 = (const float*)d_in[1];
    const float* bx0 = (const float*)d_in[2];
    const float* bx1 = (const float*)d_in[3];
    const float* tb0 = (const float*)d_in[4];
    const float* tb1 = (const float*)d_in[5];
    const int*   id0 = (const int*)d_in[6];
    const int*   id1 = (const int*)d_in[7];
    float* out = (float*)d_out;

    size_t smem = sizeof(CostSmem) > sizeof(MatchSmem)
                ? sizeof(CostSmem) : sizeof(MatchSmem);
    cudaFuncSetAttribute(fused_kernel,
                         cudaFuncAttributeMaxDynamicSharedMemorySize, (int)smem);

    fused_kernel<<<NMATCH + 2 * NCOSTB, CTH, smem>>>(
        lg0, lg1, bx0, bx1, tb0, tb1, id0, id1, out);
}

// round 16
// speedup vs baseline: 1.0403x; 1.0403x over previous
#include <cuda_runtime.h>
#include <math.h>

#define BSZ 32
#define QN  600
#define NC  152
#define TT  32
#define NT  1024          // BSZ*TT
#define NR  19200         // BSZ*QN

#define CTH 512           // 16 warps
#define NMATCH 64
#define NCOSTB 600        // cost blocks per which: NR / 32

// per-match-block diagonal tile: g_tile[blk][q][t]
__device__ float g_tile[NMATCH][QN][TT];

__device__ __forceinline__ unsigned fmap(float f) {
    unsigned b = __float_as_uint(f);
    return b ^ (unsigned)(((int)b >> 31) | 0x80000000);
}
__device__ __forceinline__ float funmap(unsigned m) {
    return __uint_as_float((m & 0x80000000u) ? (m ^ 0x80000000u) : ~m);
}

#define PSTRIDE 153
struct CostSmem {                  // ~21.1 KB
    float s_prob[32][PSTRIDE];     // (softmax prob - 1) per row
    float s_rbox[32][12];          // cx,cy,w,h | x0,y0,x1,y1 | area,pad..
};

#define NW 16
#define KS 2
struct MatchSmem {
    float  u[34];
    unsigned long long s_rm[TT];
    unsigned long long red[2][NW];
    int    rowarg[TT];
    int    unrows[TT];
    int    nun_s, cnt;
    int    sq[TT], sr[TT];
    int    way[QN];
    int    p[QN];
    float4 t_box[TT];
    float4 t_xy[TT];
    float  t_ta[TT];
    int    t_id[TT];
};

// ---------------------------------------------------------------------------
// cost for one (pred, target) pair. Takes (prob - 1); two MUFU reciprocals:
// cost = l1 - (prob-1) - inter*rcp(uni) - uni*rcp(ac)
// ---------------------------------------------------------------------------
__device__ __forceinline__ float pair_cost(
    float ocx, float ocy, float ow, float oh,
    float ox0, float oy0, float ox1, float oy1, float oarea,
    float tcx, float tcy, float tw, float th,
    float tx0, float ty0, float tx1, float ty1, float ta, float probm1)
{
    float l1 = fabsf(ocx - tcx) + fabsf(ocy - tcy)
             + fabsf(ow - tw)  + fabsf(oh - th);
    float ltx = fmaxf(ox0, tx0), lty = fmaxf(oy0, ty0);
    float rbx = fminf(ox1, tx1), rby = fminf(oy1, ty1);
    float iwr = rbx - ltx, ihr = rby - lty;
    float inter = fmaxf(iwr, 0.f) * fmaxf(ihr, 0.f);
    float uni   = oarea + ta - inter;
    float wc = ow + tw - iwr;          // enclosing width (identity, exact)
    float hc = oh + th - ihr;
    float ac = wc * hc;
    float rcpu = __fdividef(1.f, uni); // MUFU.RCP
    float rcpa = __fdividef(1.f, ac);  // MUFU.RCP
    float c = l1 - probm1;
    c = fmaf(-inter, rcpu, c);
    c = fmaf(-uni,  rcpa, c);
    return c;
}

// ---------------------------------------------------------------------------
// Cost path: 32 rows/block (2 rows per warp preamble); targets resident in
// registers (2 adjacent per lane); paired float2 streaming store; unroll 4.
// ---------------------------------------------------------------------------
__device__ void run_cost(
    CostSmem& sm, int xb, int which,
    const float* __restrict__ logits, const float* __restrict__ boxes,
    const float* __restrict__ tbbox,  const int* __restrict__ tids,
    float* __restrict__ out)
{
    float* __restrict__ C = out + (size_t)which * ((size_t)NR * NT);
    const int tid = threadIdx.x;
    const int warp = tid >> 5, lane = tid & 31;
    const int row0 = xb * 32;

    // preamble: warp w handles rows 2w, 2w+1 (softmax + row box table)
    #pragma unroll
    for (int rr = 0; rr < 2; rr++) {
        const int r = warp * 2 + rr;
        const int row = row0 + r;
        const float* lrow = logits + (size_t)row * NC;
        float rg[5], m = -1e30f;
        #pragma unroll
        for (int jj = 0; jj < 5; jj++) {
            int k = lane + 32 * jj;
            rg[jj] = (k < NC) ? lrow[k] : -1e30f;
            m = fmaxf(m, rg[jj]);
        }
        #pragma unroll
        for (int o = 16; o; o >>= 1) m = fmaxf(m, __shfl_xor_sync(~0u, m, o));
        float s = 0.f;
        #pragma unroll
        for (int jj = 0; jj < 5; jj++) {
            int k = lane + 32 * jj;
            if (k < NC) { rg[jj] = __expf(rg[jj] - m); s += rg[jj]; }
        }
        #pragma unroll
        for (int o = 16; o; o >>= 1) s += __shfl_xor_sync(~0u, s, o);
        const float inv = __fdividef(1.f, s);
        #pragma unroll
        for (int jj = 0; jj < 5; jj++) {
            int k = lane + 32 * jj;
            if (k < NC) sm.s_prob[r][k] = fmaf(rg[jj], inv, -1.0f); // prob-1
        }
        if (lane == 0) {
            float4 pb = *reinterpret_cast<const float4*>(boxes + (size_t)row * 4);
            float x0 = pb.x - 0.5f*pb.z, y0 = pb.y - 0.5f*pb.w;
            float x1 = pb.x + 0.5f*pb.z, y1 = pb.y + 0.5f*pb.w;
            sm.s_rbox[r][0] = pb.x; sm.s_rbox[r][1] = pb.y;
            sm.s_rbox[r][2] = pb.z; sm.s_rbox[r][3] = pb.w;
            sm.s_rbox[r][4] = x0;   sm.s_rbox[r][5] = y0;
            sm.s_rbox[r][6] = x1;   sm.s_rbox[r][7] = y1;
            sm.s_rbox[r][8] = (x1 - x0) * (y1 - y0);
        }
    }
    __syncthreads();

    // targets: 2 ADJACENT per lane, resident in registers
    const int t0 = warp * 64 + lane * 2;
    const float4 b0 = *reinterpret_cast<const float4*>(tbbox + (size_t)t0 * 4);
    const float4 b1 = *reinterpret_cast<const float4*>(tbbox + (size_t)(t0+1) * 4);
    const float ax0 = b0.x - 0.5f*b0.z, ay0 = b0.y - 0.5f*b0.w;
    const float ax1 = b0.x + 0.5f*b0.z, ay1 = b0.y + 0.5f*b0.w;
    const float ta0 = (ax1 - ax0) * (ay1 - ay0);
    const float bx0_ = b1.x - 0.5f*b1.z, by0_ = b1.y - 0.5f*b1.w;
    const float bx1_ = b1.x + 0.5f*b1.z, by1_ = b1.y + 0.5f*b1.w;
    const float ta1 = (bx1_ - bx0_) * (by1_ - by0_);
    const int id0 = tids[t0], id1 = tids[t0 + 1];

    float* cp = C + (size_t)row0 * NT;
    #pragma unroll 4
    for (int r = 0; r < 32; r++) {
        const float4 rc = *reinterpret_cast<const float4*>(&sm.s_rbox[r][0]);
        const float4 rx = *reinterpret_cast<const float4*>(&sm.s_rbox[r][4]);
        const float  ra = sm.s_rbox[r][8];
        const float pr0 = sm.s_prob[r][id0];
        const float pr1 = sm.s_prob[r][id1];
        float2 v;
        v.x = pair_cost(rc.x, rc.y, rc.z, rc.w,
                        rx.x, rx.y, rx.z, rx.w, ra,
                        b0.x, b0.y, b0.z, b0.w,
                        ax0, ay0, ax1, ay1, ta0, pr0);
        v.y = pair_cost(rc.x, rc.y, rc.z, rc.w,
                        rx.x, rx.y, rx.z, rx.w, ra,
                        b1.x, b1.y, b1.z, b1.w,
                        bx0_, by0_, bx1_, by1_, ta1, pr1);
        __stcs(reinterpret_cast<float2*>(cp + t0), v);   // STG.64
        cp += NT;
    }
}

// ---------------------------------------------------------------------------
// Match path: self-computed diag tile -> g_tile, rowmin warm start, exact
// Dijkstra finish, ranked emit. 512 threads.
// ---------------------------------------------------------------------------
__device__ void run_match(
    MatchSmem& sm, int bi, int b, int which,
    const float* __restrict__ logits, const float* __restrict__ boxes,
    const float* __restrict__ tbbox,  const int* __restrict__ tids,
    float* __restrict__ outbase)
{
    const int tid  = threadIdx.x;
    const int warp = tid >> 5, lane = tid & 31;

    if (tid < TT) {
        int j = b * TT + tid;
        float4 t = *reinterpret_cast<const float4*>(tbbox + (size_t)j * 4);
        sm.t_box[tid] = t;
        float x0 = t.x - 0.5f*t.z, y0 = t.y - 0.5f*t.w;
        float x1 = t.x + 0.5f*t.z, y1 = t.y + 0.5f*t.w;
        sm.t_xy[tid] = make_float4(x0, y0, x1, y1);
        sm.t_ta[tid] = (x1 - x0) * (y1 - y0);
        sm.t_id[tid] = tids[j];
        sm.s_rm[tid] = ~0ull;
    }
    for (int j = tid; j < QN; j += CTH) sm.p[j] = 0;
    __syncthreads();

    // build tile: warp per prediction row q (stride NW); lane = target t
    const int t = lane;
    const float4 tb  = sm.t_box[t];
    const float4 txy = sm.t_xy[t];
    const float  ta  = sm.t_ta[t];
    const int    tclass = sm.t_id[t];
    unsigned long long lmin = ~0ull;

    for (int q = warp; q < QN; q += NW) {
        const float* lrow = logits + (size_t)(b * QN + q) * NC;
        float r[5], m = -1e30f;
        #pragma unroll
        for (int jj = 0; jj < 5; jj++) {
            int kk = lane + 32 * jj;
            r[jj] = (kk < NC) ? lrow[kk] : -1e30f;
            m = fmaxf(m, r[jj]);
        }
        #pragma unroll
        for (int o = 16; o; o >>= 1) m = fmaxf(m, __shfl_xor_sync(~0u, m, o));
        float s = 0.f;
        #pragma unroll
        for (int jj = 0; jj < 5; jj++) {
            int kk = lane + 32 * jj;
            if (kk < NC) s += __expf(r[jj] - m);
        }
        #pragma unroll
        for (int o = 16; o; o >>= 1) s += __shfl_xor_sync(~0u, s, o);
        const float inv = __fdividef(1.f, s);

        const float4 pb = *reinterpret_cast<const float4*>(boxes + (size_t)(b*QN + q)*4);
        const float ox0 = pb.x - 0.5f*pb.z, oy0 = pb.y - 0.5f*pb.w;
        const float ox1 = pb.x + 0.5f*pb.z, oy1 = pb.y + 0.5f*pb.w;
        const float oarea = (ox1 - ox0) * (oy1 - oy0);

        const float probm1 = fmaf(__expf(lrow[tclass] - m), inv, -1.0f);
        const float val = pair_cost(pb.x, pb.y, pb.z, pb.w,
                                    ox0, oy0, ox1, oy1, oarea,
                                    tb.x, tb.y, tb.z, tb.w,
                                    txy.x, txy.y, txy.z, txy.w, ta, probm1);
        g_tile[bi][q][t] = val;
        unsigned long long key = ((unsigned long long)fmap(val) << 32) | (unsigned)q;
        lmin = min(lmin, key);
    }
    atomicMin(&sm.s_rm[lane], lmin);
    __syncthreads();

    if (tid < TT) {
        unsigned long long key = sm.s_rm[tid];
        sm.u[tid + 1]  = funmap((unsigned)(key >> 32));
        sm.rowarg[tid] = (int)(unsigned)key;
    }
    __syncthreads();

    // greedy tight-edge warm start
    if (tid == 0) {
        int nun = 0;
        for (int i = 1; i <= TT; i++) {
            int q = sm.rowarg[i - 1];
            if (sm.p[q] == 0) sm.p[q] = i;
            else sm.unrows[nun++] = i;
        }
        sm.nun_s = nun;
    }
    __syncthreads();
    const int nun = sm.nun_s;

    // shortest augmenting paths for leftover rows
    const int c_[KS] = { tid, tid + CTH };
    float v_[KS] = {0.f, 0.f};
    int par = 0;

    for (int ii = 0; ii < nun; ii++) {
        const int i = sm.unrows[ii];
        float s_[KS] = {1e30f, 1e30f};
        int usedm = (c_[1] < QN) ? 0 : 2;
        int j0 = -1, i0 = i, jf;
        float off = 0.f;

        for (;;) {
            #pragma unroll
            for (int k = 0; k < KS; k++)
                if (j0 == c_[k]) usedm |= 1 << k;

            const float ui0p = sm.u[i0] - off;
            const int   trow = i0 - 1;

            float lm = 1e30f; int lidx = 0x7fffffff;
            #pragma unroll
            for (int k = 0; k < KS; k++) {
                if (!((usedm >> k) & 1)) {
                    float cur = g_tile[bi][c_[k]][trow] - ui0p - v_[k];
                    if (cur < s_[k]) { s_[k] = cur; sm.way[c_[k]] = j0; }
                    if (s_[k] < lm) { lm = s_[k]; lidx = c_[k]; }
                }
            }
            unsigned mu   = fmap(lm);
            unsigned wmin = __reduce_min_sync(~0u, mu);
            unsigned cand = (mu == wmin) ? (unsigned)lidx : 0xffffffffu;
            unsigned widx = __reduce_min_sync(~0u, cand);
            if (lane == 0)
                sm.red[par][warp] = ((unsigned long long)wmin << 32) | widx;
            __syncthreads();
            unsigned long long bp = sm.red[par][0];
            #pragma unroll
            for (int w = 1; w < NW; w++) bp = min(bp, sm.red[par][w]);
            par ^= 1;
            off = funmap((unsigned)(bp >> 32));
            const int bj = (int)(unsigned)bp;
            const int prj = sm.p[bj];
            if (prj == 0) { jf = bj; break; }
            i0 = prj; j0 = bj;
        }

        #pragma unroll
        for (int k = 0; k < KS; k++) {
            if (((usedm >> k) & 1) && c_[k] < QN) {
                float dv = off - s_[k];
                v_[k] -= dv;
                sm.u[sm.p[c_[k]]] += dv;
            }
        }
        __syncthreads();
        if (tid == 0) {
            sm.u[i] += off;
            int j = jf;
            for (;;) {
                int jp = sm.way[j];
                sm.p[j] = (jp < 0) ? i : sm.p[jp];
                if (jp < 0) break;
                j = jp;
            }
        }
        __syncthreads();
    }

    // emit: compact assigned pairs, rank by column, write
    if (tid == 0) sm.cnt = 0;
    __syncthreads();
    #pragma unroll
    for (int k = 0; k < KS; k++) {
        int q = c_[k];
        if (q < QN && sm.p[q]) {
            int tt = atomicAdd(&sm.cnt, 1);
            sm.sq[tt] = q;
            sm.sr[tt] = sm.p[q] - 1;
        }
    }
    __syncthreads();
    if (tid < TT) {
        int q = sm.sq[tid], r = sm.sr[tid];
        int rank = 0;
        #pragma unroll
        for (int o = 0; o < TT; o++)
            rank += (__shfl_sync(~0u, q, o) < q) ? 1 : 0;
        float* op = outbase + (size_t)2 * NR * NT + (size_t)which * 2 * NT; // ps/po
        float* ot = op + NT;                                                // ts/to
        op[b * TT + rank] = (float)q;
        ot[b * TT + rank] = (float)r;
    }
}

// ---------------------------------------------------------------------------
// Fused kernel: blocks [0,64) = match (wave-1, hidden under cost), rest cost.
// ---------------------------------------------------------------------------
__global__ __launch_bounds__(CTH, 2) void fused_kernel(
    const float* __restrict__ lg0, const float* __restrict__ lg1,
    const float* __restrict__ bx0, const float* __restrict__ bx1,
    const float* __restrict__ tb0, const float* __restrict__ tb1,
    const int*   __restrict__ id0, const int*   __restrict__ id1,
    float* __restrict__ out)
{
    extern __shared__ unsigned char smem_raw[];
    const int bi = blockIdx.x;

    if (bi < NMATCH) {
        const int b = bi & 31, which = bi >> 5;
        run_match(*reinterpret_cast<MatchSmem*>(smem_raw), bi, b, which,
                  which ? lg1 : lg0, which ? bx1 : bx0,
                  which ? tb1 : tb0, which ? id1 : id0, out);
    } else {
        const int cb = bi - NMATCH;
        const int which = cb / NCOSTB, xb = cb % NCOSTB;
        run_cost(*reinterpret_cast<CostSmem*>(smem_raw), xb, which,
                 which ? lg1 : lg0, which ? bx1 : bx0,
                 which ? tb1 : tb0, which ? id1 : id0, out);
    }
}

// ---------------------------------------------------------------------------
extern "C" void kernel_launch(void* const* d_in, const int* in_sizes, int n_in,
                              void* d_out, int out_size) {
    const float* lg0 = (const float*)d_in[0];
    const float* lg1 = (const float*)d_in[1];
    const float* bx0 = (const float*)d_in[2];
    const float* bx1 = (const float*)d_in[3];
    const float* tb0 = (const float*)d_in[4];
    const float* tb1 = (const float*)d_in[5];
    const int*   id0 = (const int*)d_in[6];
    const int*   id1 = (const int*)d_in[7];
    float* out = (float*)d_out;

    size_t smem = sizeof(CostSmem) > sizeof(MatchSmem)
                ? sizeof(CostSmem) : sizeof(MatchSmem);
    cudaFuncSetAttribute(fused_kernel,
                         cudaFuncAttributeMaxDynamicSharedMemorySize, (int)smem);

    fused_kernel<<<NMATCH + 2 * NCOSTB, CTH, smem>>>(
        lg0, lg1, bx0, bx1, tb0, tb1, id0, id1, out);
}